// round 5
// baseline (speedup 1.0000x reference)
#include <cuda_runtime.h>
#include <cuda_bf16.h>
#include <math.h>
#include <stdint.h>

#define T_LEN 8192
#define HALF  4096
#define CH    128
#define BATCH 16
#define NSIG  (BATCH * CH)
#define KSPLIT 8
#define KC    32                          // K per chunk
#define NC    (T_LEN / KSPLIT / KC)       // 32 chunks per CTA
#define ROWSTRIDE 40                      // bf16 elems per smem row (32 + 8 pad)
#define MATBYTES (128 * ROWSTRIDE * 2)    // 10240
#define BUFBYTES (4 * MATBYTES)           // 40960

// Scratch (alloc-free rule: __device__ globals)
__device__ __nv_bfloat16 g_ph[(size_t)BATCH * 256 * T_LEN];   // hi parts: 64 MB
__device__ __nv_bfloat16 g_pl[(size_t)BATCH * 256 * T_LEN];   // lo parts: 64 MB
__device__ float g_gram[(size_t)KSPLIT * BATCH * 3 * CH * CH];// Gram tiles: 24 MB

// ===========================================================================
// PTX helpers (sm_103 family-portable only: ldmatrix / mma.sync / cp.async)
// ===========================================================================
__device__ __forceinline__ uint32_t smem_u32(const void* p) {
    uint32_t a;
    asm("{ .reg .u64 t; cvta.to.shared.u64 t, %1; cvt.u32.u64 %0, t; }"
        : "=r"(a) : "l"(p));
    return a;
}
__device__ __forceinline__ void ldsm4(uint32_t* d, uint32_t addr) {
    asm volatile("ldmatrix.sync.aligned.m8n8.x4.shared.b16 {%0,%1,%2,%3}, [%4];"
                 : "=r"(d[0]), "=r"(d[1]), "=r"(d[2]), "=r"(d[3]) : "r"(addr));
}
__device__ __forceinline__ void ldsm2(uint32_t* d, uint32_t addr) {
    asm volatile("ldmatrix.sync.aligned.m8n8.x2.shared.b16 {%0,%1}, [%2];"
                 : "=r"(d[0]), "=r"(d[1]) : "r"(addr));
}
__device__ __forceinline__ void mma_bf16(float* d, const uint32_t* a, const uint32_t* b) {
    asm volatile(
        "mma.sync.aligned.m16n8k16.row.col.f32.bf16.bf16.f32 "
        "{%0,%1,%2,%3}, {%4,%5,%6,%7}, {%8,%9}, {%0,%1,%2,%3};"
        : "+f"(d[0]), "+f"(d[1]), "+f"(d[2]), "+f"(d[3])
        : "r"(a[0]), "r"(a[1]), "r"(a[2]), "r"(a[3]), "r"(b[0]), "r"(b[1]));
}
__device__ __forceinline__ void cp16(uint32_t smem, const void* g) {
    asm volatile("cp.async.cg.shared.global [%0], [%1], 16;"
                 :: "r"(smem), "l"(g) : "memory");
}
#define CP_COMMIT() asm volatile("cp.async.commit_group;" ::: "memory")
#define CP_WAIT1()  asm volatile("cp.async.wait_group 1;" ::: "memory")
#define CP_WAIT0()  asm volatile("cp.async.wait_group 0;" ::: "memory")

// ===========================================================================
// Kernel 1: register-resident FFT -> analytic signal -> unit phase vectors,
// emitted as bf16 hi/lo for cos rows [0..127] and sin rows [128..255].
// ===========================================================================
__device__ __forceinline__ int swz(int i) { return i ^ ((i >> 5) & 31); }

template<int P, int FWD, int LBLO, int LBHI>
__device__ __forceinline__ void stages(float2 v[16], int base, const float2* __restrict__ tw) {
#pragma unroll
    for (int t = 0; t <= LBHI - LBLO; t++) {
        const int lb = FWD ? (LBHI - t) : (LBLO + t);
        const int s  = P + lb;
        const int m  = 1 << s;
        const int bm = base & (m - 1);
#pragma unroll
        for (int rr = 0; rr < 16; rr++) {
            if ((rr >> lb) & 1) continue;
            const int r1 = rr | (1 << lb);
            const int j  = bm + ((rr & ((1 << lb) - 1)) << P);
            const float2 w = tw[j << (12 - s)];
            float2 a = v[rr], b = v[r1];
            if (FWD) {
                v[rr] = make_float2(a.x + b.x, a.y + b.y);
                float2 d = make_float2(a.x - b.x, a.y - b.y);
                v[r1] = make_float2(d.x * w.x - d.y * w.y, d.x * w.y + d.y * w.x);
            } else {
                float2 tt = make_float2(b.x * w.x + b.y * w.y, b.y * w.x - b.x * w.y);
                v[rr] = make_float2(a.x + tt.x, a.y + tt.y);
                v[r1] = make_float2(a.x - tt.x, a.y - tt.y);
            }
        }
    }
}

extern __shared__ float2 smm[];   // fft: [0..8191]=exchange, [8192..12287]=twiddles

__global__ void __launch_bounds__(512) fft_kernel(const float* __restrict__ x) {
    float2* sm = smm;
    float2* tw = smm + T_LEN;
    const int tid = threadIdx.x;
    const long long gbase = (long long)blockIdx.x * T_LEN;

    for (int t = tid; t < HALF; t += 512) {
        float s, c;
        sincosf(-6.283185307179586e0f * (float)t / (float)T_LEN, &s, &c);
        tw[t] = make_float2(c, s);
    }

    const int baseA = tid;
    const int baseB = ((tid >> 5) << 9) + (tid & 31);
    const int baseC = ((tid >> 1) << 5) + (tid & 1);
    const int baseD = tid << 4;
    const int baseE = ((tid >> 4) << 8) + (tid & 15);
    const int baseF = ((tid >> 8) << 12) + (tid & 255);

    float2 v[16];
#pragma unroll
    for (int r = 0; r < 16; r++)
        v[r] = make_float2(x[gbase + tid + r * 512], 0.0f);
    __syncthreads();

    stages<9, 1, 0, 3>(v, baseA, tw);
#pragma unroll
    for (int r = 0; r < 16; r++) sm[swz(baseA + (r << 9))] = v[r];
    __syncthreads();
#pragma unroll
    for (int r = 0; r < 16; r++) v[r] = sm[swz(baseB + (r << 5))];
    __syncthreads();

    stages<5, 1, 0, 3>(v, baseB, tw);
#pragma unroll
    for (int r = 0; r < 16; r++) sm[swz(baseB + (r << 5))] = v[r];
    __syncthreads();
#pragma unroll
    for (int r = 0; r < 16; r++) v[r] = sm[swz(baseC + (r << 1))];
    __syncthreads();

    stages<1, 1, 0, 3>(v, baseC, tw);
#pragma unroll
    for (int r = 0; r < 16; r++) sm[swz(baseC + (r << 1))] = v[r];
    __syncthreads();
#pragma unroll
    for (int r = 0; r < 16; r++) v[r] = sm[swz(baseD + r)];
    __syncthreads();

#pragma unroll
    for (int r = 0; r < 16; r += 2) {
        float2 s0 = make_float2(v[r].x + v[r + 1].x, v[r].y + v[r + 1].y);
        v[r] = s0; v[r + 1] = s0;
    }

    stages<0, 0, 1, 3>(v, baseD, tw);
#pragma unroll
    for (int r = 0; r < 16; r++) sm[swz(baseD + r)] = v[r];
    __syncthreads();
#pragma unroll
    for (int r = 0; r < 16; r++) v[r] = sm[swz(baseE + (r << 4))];
    __syncthreads();

    stages<4, 0, 0, 3>(v, baseE, tw);
#pragma unroll
    for (int r = 0; r < 16; r++) sm[swz(baseE + (r << 4))] = v[r];
    __syncthreads();
#pragma unroll
    for (int r = 0; r < 16; r++) v[r] = sm[swz(baseF + (r << 8))];
    __syncthreads();

    stages<8, 0, 0, 3>(v, baseF, tw);
#pragma unroll
    for (int r = 0; r < 16; r++) sm[swz(baseF + (r << 8))] = v[r];
    __syncthreads();
#pragma unroll
    for (int r = 0; r < 16; r++) v[r] = sm[swz(baseA + (r << 9))];
    __syncthreads();

    stages<9, 0, 3, 3>(v, baseA, tw);

    const int bb = blockIdx.x >> 7;
    const int cc = blockIdx.x & 127;
    const size_t rowc = ((size_t)bb * 256 + cc) * T_LEN;
    const size_t rows = rowc + (size_t)128 * T_LEN;
#pragma unroll
    for (int r = 0; r < 16; r++) {
        const int t = tid + r * 512;
        float2 u = v[r];
        float m2 = u.x * u.x + u.y * u.y;
        float cx, sx;
        if (m2 > 0.0f) {
            float inv = rsqrtf(m2);
            cx = u.x * inv; sx = u.y * inv;
        } else {
            cx = 1.0f; sx = 0.0f;
        }
        __nv_bfloat16 chh = __float2bfloat16(cx);
        __nv_bfloat16 cll = __float2bfloat16(cx - __bfloat162float(chh));
        __nv_bfloat16 shh = __float2bfloat16(sx);
        __nv_bfloat16 sll = __float2bfloat16(sx - __bfloat162float(shh));
        g_ph[rowc + t] = chh;  g_pl[rowc + t] = cll;
        g_ph[rows + t] = shh;  g_pl[rows + t] = sll;
    }
}

// ===========================================================================
// Kernel 2: bf16 hi/lo-split Gram via mma.sync.m16n8k16 (HMMA).
// CTA = (ks, tile, b). tiles: 0=(0,0)=CC, 1=(1,1)=SS, 2=(1,0)=SC.
// D[128x128] += Hi*Hi^T + Hi*Lo^T + Lo*Hi^T over this CTA's K range.
// ===========================================================================
extern __shared__ __align__(128) char gsm[];   // 2 * BUFBYTES = 80 KB

__global__ void __launch_bounds__(256) gram_mma() {
    const int tid  = threadIdx.x;
    const int wid  = tid >> 5;
    const int lane = tid & 31;
    const int ks   = blockIdx.x;
    const int tile = blockIdx.y;
    const int b    = blockIdx.z;
    const int ms   = (tile >= 1) ? 1 : 0;
    const int ns   = (tile == 1) ? 1 : 0;
    const bool diag = (ms == ns);

    const uint32_t sb = smem_u32(gsm);
    const size_t k0 = (size_t)ks * (T_LEN / KSPLIT);

    // ---- loader state: 4 quads (16B) per virtual row, 64 vrows per pass ----
    const int sub  = tid & 3;        // 16B quad within 64B row-chunk
    const int vrw  = tid >> 2;       // 0..63
    const int npass = diag ? 4 : 8;  // (diag: only A matrices)

    // Per-pass constants
    int prow[8]; const __nv_bfloat16* psrc[8]; uint32_t pdst[8];
#pragma unroll
    for (int p = 0; p < 8; p++) {
        const int vr = vrw + p * 64;        // 0..511
        const int q  = vr >> 7;             // matrix: 0=Ahi 1=Alo 2=Bhi 3=Blo
        const int r  = vr & 127;
        psrc[p] = (q & 1) ? g_pl : g_ph;
        prow[p] = (b * 256 + ((q < 2) ? ms : ns) * 128 + r);
        pdst[p] = (uint32_t)(q * MATBYTES + r * (ROWSTRIDE * 2) + sub * 16);
    }

    // issue async load of chunk c into buffer c&1
    auto load_chunk = [&](int c) {
        const uint32_t bufb = sb + (uint32_t)((c & 1) * BUFBYTES);
        const size_t kofs = k0 + (size_t)c * KC + sub * 8;
#pragma unroll
        for (int p = 0; p < 8; p++) {
            if (p >= npass) break;
            cp16(bufb + pdst[p], psrc[p] + (size_t)prow[p] * T_LEN + kofs);
        }
        CP_COMMIT();
    };

    // ---- compute state ----
    const int mrow0 = (wid >> 2) * 64;    // warp m block (0 or 64)
    const int ncol0 = (wid & 3) * 32;     // warp n block (0,32,64,96)

    float acc[4][4][4];
#pragma unroll
    for (int mt = 0; mt < 4; mt++)
#pragma unroll
        for (int nt = 0; nt < 4; nt++)
#pragma unroll
            for (int e = 0; e < 4; e++) acc[mt][nt][e] = 0.0f;

    const uint32_t bOfsHi = diag ? 0u : (uint32_t)(2 * MATBYTES);
    const uint32_t bOfsLo = diag ? (uint32_t)MATBYTES : (uint32_t)(3 * MATBYTES);

    load_chunk(0);
    for (int c = 0; c < NC; c++) {
        if (c + 1 < NC) { load_chunk(c + 1); CP_WAIT1(); }
        else           { CP_WAIT0(); }
        __syncthreads();

        const uint32_t bufb = sb + (uint32_t)((c & 1) * BUFBYTES);
#pragma unroll
        for (int kstep = 0; kstep < KC / 16; kstep++) {
            uint32_t ah[4][4], al[4][4], bh[4][2], bl[4][2];
            const int arow  = mrow0 + (lane & 15);
            const int acolb = (((lane >> 4) << 3) + kstep * 16) * 2;
#pragma unroll
            for (int mt = 0; mt < 4; mt++) {
                const uint32_t ao = (uint32_t)((arow + mt * 16) * (ROWSTRIDE * 2) + acolb);
                ldsm4(ah[mt], bufb + ao);
                ldsm4(al[mt], bufb + MATBYTES + ao);
            }
            const int brow  = ncol0 + (lane & 7);
            const int bcolb = ((((lane >> 3) & 1) << 3) + kstep * 16) * 2;
#pragma unroll
            for (int nt = 0; nt < 4; nt++) {
                const uint32_t bo = (uint32_t)((brow + nt * 8) * (ROWSTRIDE * 2) + bcolb);
                ldsm2(bh[nt], bufb + bOfsHi + bo);
                ldsm2(bl[nt], bufb + bOfsLo + bo);
            }
#pragma unroll
            for (int mt = 0; mt < 4; mt++)
#pragma unroll
                for (int nt = 0; nt < 4; nt++) {
                    mma_bf16(acc[mt][nt], ah[mt], bh[nt]);
                    mma_bf16(acc[mt][nt], ah[mt], bl[nt]);
                    mma_bf16(acc[mt][nt], al[mt], bh[nt]);
                }
        }
        __syncthreads();
    }

    // ---- epilogue: fragment -> gmem (float2 stores) ----
    float* __restrict__ G =
        g_gram + ((size_t)((ks * BATCH + b) * 3 + tile)) * (CH * CH);
    const int r0 = lane >> 2;
    const int c0 = (lane & 3) * 2;
#pragma unroll
    for (int mt = 0; mt < 4; mt++) {
        const int row = mrow0 + mt * 16 + r0;
#pragma unroll
        for (int nt = 0; nt < 4; nt++) {
            const int col = ncol0 + nt * 8 + c0;
            *(float2*)(G + row * CH + col) =
                make_float2(acc[mt][nt][0], acc[mt][nt][1]);
            *(float2*)(G + (row + 8) * CH + col) =
                make_float2(acc[mt][nt][2], acc[mt][nt][3]);
        }
    }
}

// ===========================================================================
// Kernel 3: combine K-splits; Re = CC+SS, Im = SC[i,j]-SC[j,i]; PLV=|.|/T.
// ===========================================================================
__global__ void finalize_kernel(float* __restrict__ out) {
    const int idx = blockIdx.x * blockDim.x + threadIdx.x;
    if (idx >= BATCH * CH * CH) return;
    const int b  = idx >> 14;
    const int ij = idx & 16383;
    const int i  = ij >> 7;
    const int j  = ij & 127;
    float re = 0.0f, im = 0.0f;
#pragma unroll
    for (int ks = 0; ks < KSPLIT; ks++) {
        const float* __restrict__ base =
            g_gram + ((size_t)((ks * BATCH + b) * 3)) * (CH * CH);
        re += base[ij] + base[CH * CH + ij];                       // CC + SS
        im += base[2 * CH * CH + i * CH + j]
            - base[2 * CH * CH + j * CH + i];                      // SC - SC^T
    }
    out[idx] = sqrtf(re * re + im * im) * (1.0f / (float)T_LEN);
}

// ===========================================================================
extern "C" void kernel_launch(void* const* d_in, const int* in_sizes, int n_in,
                              void* d_out, int out_size) {
    const float* x = (const float*)d_in[0];
    float* out = (float*)d_out;

    const int fft_smem = (T_LEN + HALF) * (int)sizeof(float2);  // 96 KB
    cudaFuncSetAttribute(fft_kernel, cudaFuncAttributeMaxDynamicSharedMemorySize,
                         fft_smem);
    cudaFuncSetAttribute(gram_mma, cudaFuncAttributeMaxDynamicSharedMemorySize,
                         2 * BUFBYTES);

    fft_kernel<<<NSIG, 512, fft_smem>>>(x);
    gram_mma<<<dim3(KSPLIT, 3, BATCH), 256, 2 * BUFBYTES>>>();
    finalize_kernel<<<(BATCH * CH * CH + 255) / 256, 256>>>(out);
}

// round 6
// speedup vs baseline: 1.4331x; 1.4331x over previous
#include <cuda_runtime.h>
#include <cuda_bf16.h>
#include <math.h>
#include <stdint.h>

#define T_LEN 8192
#define HALF  4096
#define CH    128
#define BATCH 16
#define NSIG  (BATCH * CH)
#define KSPLIT 16
#define KC    32                          // K per chunk
#define NC    (T_LEN / KSPLIT / KC)       // 16 chunks per CTA
#define ROWSTRIDE 40                      // bf16 elems per smem row (32 + 8 pad)
#define MATBYTES (128 * ROWSTRIDE * 2)    // 10240
#define BUFBYTES (4 * MATBYTES)           // 40960

// Scratch (alloc-free rule: __device__ globals)
__device__ __nv_bfloat16 g_ph[(size_t)BATCH * 256 * T_LEN];   // hi parts: 64 MB
__device__ __nv_bfloat16 g_pl[(size_t)BATCH * 256 * T_LEN];   // lo parts: 64 MB
__device__ float g_gram[(size_t)KSPLIT * BATCH * 3 * CH * CH];// Gram tiles: 48 MB

// ===========================================================================
// PTX helpers (sm_103 family-portable: ldmatrix / mma.sync / cp.async)
// ===========================================================================
__device__ __forceinline__ uint32_t smem_u32(const void* p) {
    uint32_t a;
    asm("{ .reg .u64 t; cvta.to.shared.u64 t, %1; cvt.u32.u64 %0, t; }"
        : "=r"(a) : "l"(p));
    return a;
}
__device__ __forceinline__ void ldsm4(uint32_t* d, uint32_t addr) {
    asm volatile("ldmatrix.sync.aligned.m8n8.x4.shared.b16 {%0,%1,%2,%3}, [%4];"
                 : "=r"(d[0]), "=r"(d[1]), "=r"(d[2]), "=r"(d[3]) : "r"(addr));
}
__device__ __forceinline__ void ldsm2(uint32_t* d, uint32_t addr) {
    asm volatile("ldmatrix.sync.aligned.m8n8.x2.shared.b16 {%0,%1}, [%2];"
                 : "=r"(d[0]), "=r"(d[1]) : "r"(addr));
}
__device__ __forceinline__ void mma_bf16(float* d, const uint32_t* a, const uint32_t* b) {
    asm volatile(
        "mma.sync.aligned.m16n8k16.row.col.f32.bf16.bf16.f32 "
        "{%0,%1,%2,%3}, {%4,%5,%6,%7}, {%8,%9}, {%0,%1,%2,%3};"
        : "+f"(d[0]), "+f"(d[1]), "+f"(d[2]), "+f"(d[3])
        : "r"(a[0]), "r"(a[1]), "r"(a[2]), "r"(a[3]), "r"(b[0]), "r"(b[1]));
}
__device__ __forceinline__ void cp16(uint32_t smem, const void* g) {
    asm volatile("cp.async.cg.shared.global [%0], [%1], 16;"
                 :: "r"(smem), "l"(g) : "memory");
}
#define CP_COMMIT() asm volatile("cp.async.commit_group;" ::: "memory")
#define CP_WAIT1()  asm volatile("cp.async.wait_group 1;" ::: "memory")
#define CP_WAIT0()  asm volatile("cp.async.wait_group 0;" ::: "memory")

// ===========================================================================
// Kernel 1: register-resident FFT -> analytic signal -> unit phase vectors.
// Epilogue stages bf16 hi/lo results through smem and writes STG.128 only.
// ===========================================================================
__device__ __forceinline__ int swz(int i) { return i ^ ((i >> 5) & 31); }

template<int P, int FWD, int LBLO, int LBHI>
__device__ __forceinline__ void stages(float2 v[16], int base, const float2* __restrict__ tw) {
#pragma unroll
    for (int t = 0; t <= LBHI - LBLO; t++) {
        const int lb = FWD ? (LBHI - t) : (LBLO + t);
        const int s  = P + lb;
        const int m  = 1 << s;
        const int bm = base & (m - 1);
#pragma unroll
        for (int rr = 0; rr < 16; rr++) {
            if ((rr >> lb) & 1) continue;
            const int r1 = rr | (1 << lb);
            const int j  = bm + ((rr & ((1 << lb) - 1)) << P);
            const float2 w = tw[j << (12 - s)];
            float2 a = v[rr], b = v[r1];
            if (FWD) {
                v[rr] = make_float2(a.x + b.x, a.y + b.y);
                float2 d = make_float2(a.x - b.x, a.y - b.y);
                v[r1] = make_float2(d.x * w.x - d.y * w.y, d.x * w.y + d.y * w.x);
            } else {
                float2 tt = make_float2(b.x * w.x + b.y * w.y, b.y * w.x - b.x * w.y);
                v[rr] = make_float2(a.x + tt.x, a.y + tt.y);
                v[r1] = make_float2(a.x - tt.x, a.y - tt.y);
            }
        }
    }
}

extern __shared__ float2 smm[];   // fft: [0..8191]=exchange, [8192..12287]=twiddles

__global__ void __launch_bounds__(512) fft_kernel(const float* __restrict__ x) {
    float2* sm = smm;
    float2* tw = smm + T_LEN;
    const int tid = threadIdx.x;
    const long long gbase = (long long)blockIdx.x * T_LEN;

    for (int t = tid; t < HALF; t += 512) {
        float s, c;
        sincosf(-6.283185307179586e0f * (float)t / (float)T_LEN, &s, &c);
        tw[t] = make_float2(c, s);
    }

    const int baseA = tid;
    const int baseB = ((tid >> 5) << 9) + (tid & 31);
    const int baseC = ((tid >> 1) << 5) + (tid & 1);
    const int baseD = tid << 4;
    const int baseE = ((tid >> 4) << 8) + (tid & 15);
    const int baseF = ((tid >> 8) << 12) + (tid & 255);

    float2 v[16];
#pragma unroll
    for (int r = 0; r < 16; r++)
        v[r] = make_float2(x[gbase + tid + r * 512], 0.0f);
    __syncthreads();

    stages<9, 1, 0, 3>(v, baseA, tw);
#pragma unroll
    for (int r = 0; r < 16; r++) sm[swz(baseA + (r << 9))] = v[r];
    __syncthreads();
#pragma unroll
    for (int r = 0; r < 16; r++) v[r] = sm[swz(baseB + (r << 5))];
    __syncthreads();

    stages<5, 1, 0, 3>(v, baseB, tw);
#pragma unroll
    for (int r = 0; r < 16; r++) sm[swz(baseB + (r << 5))] = v[r];
    __syncthreads();
#pragma unroll
    for (int r = 0; r < 16; r++) v[r] = sm[swz(baseC + (r << 1))];
    __syncthreads();

    stages<1, 1, 0, 3>(v, baseC, tw);
#pragma unroll
    for (int r = 0; r < 16; r++) sm[swz(baseC + (r << 1))] = v[r];
    __syncthreads();
#pragma unroll
    for (int r = 0; r < 16; r++) v[r] = sm[swz(baseD + r)];
    __syncthreads();

#pragma unroll
    for (int r = 0; r < 16; r += 2) {
        float2 s0 = make_float2(v[r].x + v[r + 1].x, v[r].y + v[r + 1].y);
        v[r] = s0; v[r + 1] = s0;
    }

    stages<0, 0, 1, 3>(v, baseD, tw);
#pragma unroll
    for (int r = 0; r < 16; r++) sm[swz(baseD + r)] = v[r];
    __syncthreads();
#pragma unroll
    for (int r = 0; r < 16; r++) v[r] = sm[swz(baseE + (r << 4))];
    __syncthreads();

    stages<4, 0, 0, 3>(v, baseE, tw);
#pragma unroll
    for (int r = 0; r < 16; r++) sm[swz(baseE + (r << 4))] = v[r];
    __syncthreads();
#pragma unroll
    for (int r = 0; r < 16; r++) v[r] = sm[swz(baseF + (r << 8))];
    __syncthreads();

    stages<8, 0, 0, 3>(v, baseF, tw);
#pragma unroll
    for (int r = 0; r < 16; r++) sm[swz(baseF + (r << 8))] = v[r];
    __syncthreads();
#pragma unroll
    for (int r = 0; r < 16; r++) v[r] = sm[swz(baseA + (r << 9))];
    __syncthreads();

    stages<9, 0, 3, 3>(v, baseA, tw);

    // ---- epilogue: normalize, bf16 hi/lo split, stage in smem, wide stores.
    // smem layout (reuse 64 KB exchange region): [chi | clo | shi | slo], 16KB each
    __nv_bfloat16* sb16 = (__nv_bfloat16*)sm;
#pragma unroll
    for (int r = 0; r < 16; r++) {
        const int t = tid + r * 512;
        float2 u = v[r];
        float m2 = u.x * u.x + u.y * u.y;
        float cx, sx;
        if (m2 > 0.0f) {
            float inv = rsqrtf(m2);
            cx = u.x * inv; sx = u.y * inv;
        } else {
            cx = 1.0f; sx = 0.0f;
        }
        __nv_bfloat16 chh = __float2bfloat16(cx);
        __nv_bfloat16 cll = __float2bfloat16(cx - __bfloat162float(chh));
        __nv_bfloat16 shh = __float2bfloat16(sx);
        __nv_bfloat16 sll = __float2bfloat16(sx - __bfloat162float(shh));
        sb16[t]             = chh;
        sb16[T_LEN + t]     = cll;
        sb16[2 * T_LEN + t] = shh;
        sb16[3 * T_LEN + t] = sll;
    }
    __syncthreads();

    const int bb = blockIdx.x >> 7;
    const int cc = blockIdx.x & 127;
    const size_t rowc = ((size_t)bb * 256 + cc) * T_LEN;
    const size_t rows = rowc + (size_t)128 * T_LEN;
    const uint4* s4 = (const uint4*)sb16;      // 4096 uint4 total, 1024 per array
    {
        uint4* d0 = (uint4*)(g_ph + rowc);     // chi
        uint4* d1 = (uint4*)(g_pl + rowc);     // clo
        uint4* d2 = (uint4*)(g_ph + rows);     // shi
        uint4* d3 = (uint4*)(g_pl + rows);     // slo
        d0[tid] = s4[tid];            d0[512 + tid] = s4[512 + tid];
        d1[tid] = s4[1024 + tid];     d1[512 + tid] = s4[1536 + tid];
        d2[tid] = s4[2048 + tid];     d2[512 + tid] = s4[2560 + tid];
        d3[tid] = s4[3072 + tid];     d3[512 + tid] = s4[3584 + tid];
    }
}

// ===========================================================================
// Kernel 2: bf16 hi/lo-split Gram via mma.sync.m16n8k16.
// CTA = (ks, tile, b). tiles: 0=(0,0)=CC, 1=(1,1)=SS, 2=(1,0)=SC.
// 2 CTAs/SM via launch bounds for latency hiding.
// ===========================================================================
extern __shared__ __align__(128) char gsm[];   // 2 * BUFBYTES = 80 KB

__global__ void __launch_bounds__(256, 2) gram_mma() {
    const int tid  = threadIdx.x;
    const int wid  = tid >> 5;
    const int lane = tid & 31;
    const int ks   = blockIdx.x;
    const int tile = blockIdx.y;
    const int b    = blockIdx.z;
    const int ms   = (tile >= 1) ? 1 : 0;
    const int ns   = (tile == 1) ? 1 : 0;
    const bool diag = (ms == ns);

    const uint32_t sb = smem_u32(gsm);
    const size_t k0 = (size_t)ks * (T_LEN / KSPLIT);

    // ---- loader: 4 quads (16B) per virtual row, 64 vrows per pass ----
    const int sub  = tid & 3;
    const int vrw  = tid >> 2;
    const int npass = diag ? 4 : 8;

    int prow[8]; const __nv_bfloat16* psrc[8]; uint32_t pdst[8];
#pragma unroll
    for (int p = 0; p < 8; p++) {
        const int vr = vrw + p * 64;
        const int q  = vr >> 7;              // 0=Ahi 1=Alo 2=Bhi 3=Blo
        const int r  = vr & 127;
        psrc[p] = (q & 1) ? g_pl : g_ph;
        prow[p] = (b * 256 + ((q < 2) ? ms : ns) * 128 + r);
        pdst[p] = (uint32_t)(q * MATBYTES + r * (ROWSTRIDE * 2) + sub * 16);
    }

    auto load_chunk = [&](int c) {
        const uint32_t bufb = sb + (uint32_t)((c & 1) * BUFBYTES);
        const size_t kofs = k0 + (size_t)c * KC + sub * 8;
#pragma unroll
        for (int p = 0; p < 8; p++) {
            if (p >= npass) break;
            cp16(bufb + pdst[p], psrc[p] + (size_t)prow[p] * T_LEN + kofs);
        }
        CP_COMMIT();
    };

    const int mrow0 = (wid >> 2) * 64;
    const int ncol0 = (wid & 3) * 32;

    float acc[4][4][4];
#pragma unroll
    for (int mt = 0; mt < 4; mt++)
#pragma unroll
        for (int nt = 0; nt < 4; nt++)
#pragma unroll
            for (int e = 0; e < 4; e++) acc[mt][nt][e] = 0.0f;

    const uint32_t bOfsHi = diag ? 0u : (uint32_t)(2 * MATBYTES);
    const uint32_t bOfsLo = diag ? (uint32_t)MATBYTES : (uint32_t)(3 * MATBYTES);

    load_chunk(0);
    for (int c = 0; c < NC; c++) {
        if (c + 1 < NC) { load_chunk(c + 1); CP_WAIT1(); }
        else           { CP_WAIT0(); }
        __syncthreads();

        const uint32_t bufb = sb + (uint32_t)((c & 1) * BUFBYTES);
#pragma unroll
        for (int kstep = 0; kstep < KC / 16; kstep++) {
            // B fragments for all 4 nt (hi + lo) — 16 regs held
            uint32_t bh[4][2], bl[4][2];
            const int brow  = ncol0 + (lane & 7);
            const int bcolb = ((((lane >> 3) & 1) << 3) + kstep * 16) * 2;
#pragma unroll
            for (int nt = 0; nt < 4; nt++) {
                const uint32_t bo = (uint32_t)((brow + nt * 8) * (ROWSTRIDE * 2) + bcolb);
                ldsm2(bh[nt], bufb + bOfsHi + bo);
                ldsm2(bl[nt], bufb + bOfsLo + bo);
            }
            const int arow  = mrow0 + (lane & 15);
            const int acolb = (((lane >> 4) << 3) + kstep * 16) * 2;
#pragma unroll
            for (int mt = 0; mt < 4; mt++) {
                uint32_t ah[4], al[4];
                const uint32_t ao = (uint32_t)((arow + mt * 16) * (ROWSTRIDE * 2) + acolb);
                ldsm4(ah, bufb + ao);
                ldsm4(al, bufb + MATBYTES + ao);
#pragma unroll
                for (int nt = 0; nt < 4; nt++) {
                    mma_bf16(acc[mt][nt], ah, bh[nt]);
                    mma_bf16(acc[mt][nt], ah, bl[nt]);
                    mma_bf16(acc[mt][nt], al, bh[nt]);
                }
            }
        }
        __syncthreads();
    }

    float* __restrict__ G =
        g_gram + ((size_t)((ks * BATCH + b) * 3 + tile)) * (CH * CH);
    const int r0 = lane >> 2;
    const int c0 = (lane & 3) * 2;
#pragma unroll
    for (int mt = 0; mt < 4; mt++) {
        const int row = mrow0 + mt * 16 + r0;
#pragma unroll
        for (int nt = 0; nt < 4; nt++) {
            const int col = ncol0 + nt * 8 + c0;
            *(float2*)(G + row * CH + col) =
                make_float2(acc[mt][nt][0], acc[mt][nt][1]);
            *(float2*)(G + (row + 8) * CH + col) =
                make_float2(acc[mt][nt][2], acc[mt][nt][3]);
        }
    }
}

// ===========================================================================
// Kernel 3: combine K-splits; Re = CC+SS, Im = SC[i,j]-SC[j,i]; PLV=|.|/T.
// ===========================================================================
__global__ void finalize_kernel(float* __restrict__ out) {
    const int idx = blockIdx.x * blockDim.x + threadIdx.x;
    if (idx >= BATCH * CH * CH) return;
    const int b  = idx >> 14;
    const int ij = idx & 16383;
    const int i  = ij >> 7;
    const int j  = ij & 127;
    float re = 0.0f, im = 0.0f;
#pragma unroll
    for (int ks = 0; ks < KSPLIT; ks++) {
        const float* __restrict__ base =
            g_gram + ((size_t)((ks * BATCH + b) * 3)) * (CH * CH);
        re += base[ij] + base[CH * CH + ij];                       // CC + SS
        im += base[2 * CH * CH + i * CH + j]
            - base[2 * CH * CH + j * CH + i];                      // SC - SC^T
    }
    out[idx] = sqrtf(re * re + im * im) * (1.0f / (float)T_LEN);
}

// ===========================================================================
extern "C" void kernel_launch(void* const* d_in, const int* in_sizes, int n_in,
                              void* d_out, int out_size) {
    const float* x = (const float*)d_in[0];
    float* out = (float*)d_out;

    const int fft_smem = (T_LEN + HALF) * (int)sizeof(float2);  // 96 KB
    cudaFuncSetAttribute(fft_kernel, cudaFuncAttributeMaxDynamicSharedMemorySize,
                         fft_smem);
    cudaFuncSetAttribute(gram_mma, cudaFuncAttributeMaxDynamicSharedMemorySize,
                         2 * BUFBYTES);

    fft_kernel<<<NSIG, 512, fft_smem>>>(x);
    gram_mma<<<dim3(KSPLIT, 3, BATCH), 256, 2 * BUFBYTES>>>();
    finalize_kernel<<<(BATCH * CH * CH + 255) / 256, 256>>>(out);
}